// round 2
// baseline (speedup 1.0000x reference)
#include <cuda_runtime.h>
#include <stdint.h>
#include <math.h>

#define T_LEN 8192
#define B_CNT 16
#define NSTEP 8189          // T-3 markov samples
#define SEG_N 64
#define SEG_L 128           // SEG_N*SEG_L = 8192 (pad last 3 steps)

// ---------------- device scratch (no allocations allowed) ----------------
__device__ uint8_t g_snsp[B_CNT * T_LEN];       // per (b,t): sn | sp<<2
__device__ uint8_t g_end[B_CNT * SEG_N * 16];   // 9 end-states per (b,seg), padded to 16B
__device__ uint8_t g_smp[B_CNT * T_LEN];        // resolved markov samples per (b, st)
__device__ float   g_logits[4];                 // lp, ls, log(8/9-ish), log(1/9-ish)

// ---------------- threefry-2x32 (20 rounds), matches JAX exactly ----------------
__device__ __forceinline__ void tf2x32(uint32_t k0, uint32_t k1,
                                       uint32_t x0, uint32_t x1,
                                       uint32_t& o0, uint32_t& o1) {
    uint32_t ks2 = k0 ^ k1 ^ 0x1BD11BDAu;
    x0 += k0; x1 += k1;
#define RND(r) { x0 += x1; x1 = __funnelshift_l(x1, x1, (r)); x1 ^= x0; }
    RND(13) RND(15) RND(26) RND(6)
    x0 += k1; x1 += ks2 + 1u;
    RND(17) RND(29) RND(16) RND(24)
    x0 += ks2; x1 += k0 + 2u;
    RND(13) RND(15) RND(26) RND(6)
    x0 += k0; x1 += k1 + 3u;
    RND(17) RND(29) RND(16) RND(24)
    x0 += k1; x1 += ks2 + 4u;
    RND(13) RND(15) RND(26) RND(6)
    x0 += ks2; x1 += k0 + 5u;
#undef RND
    o0 = x0; o1 = x1;
}

// JAX uniform(minval=tiny, maxval=1) from raw bits
__device__ __forceinline__ float u_from_bits(uint32_t bits) {
    const float tiny = 1.1754943508222875e-38f;  // FLT_MIN
    float f = __uint_as_float((bits >> 9) | 0x3f800000u) - 1.0f;
    return fmaxf(tiny, f + tiny);                // f*(1-tiny)+tiny == f+tiny in f32
}

__device__ __forceinline__ float gum_fast(uint32_t bits) {
    float u = u_from_bits(bits);
    return -logf(-logf(u));
}

// correctly-rounded f32 gumbel via double logs (used only when argmax margin is tight)
__device__ float gum_precise(uint32_t bits) {
    float u = u_from_bits(bits);
    float inner = (float)log((double)u);
    return -(float)log((double)(-inner));
}

// ---------------- K0: logit constants (built like the numpy reference) -------------
__global__ void k0_init() {
    double p = 0.1;                 // REPLACE_PROB (python double)
    double s = 1.0 - 2.0 * p;
    g_logits[0] = (float)log((double)(float)p);            // log(f32(0.1))
    g_logits[1] = (float)log((double)(float)s);            // log(f32(0.8))
    g_logits[2] = (float)log((double)(float)(s / (p + s))); // special row k=1
    g_logits[3] = (float)log((double)(float)(p / (p + s))); // special row k=2
}

// ---------------- K1: per-(t,b) candidate samples sn / sp ----------------
// PARTITIONABLE threefry (modern JAX default):
//   keys[t]      = tf(key, 0, t)                    (both output words)
//   bits[(16,3)] : element j -> o0 ^ o1 of tf(key_t, 0, j)
__global__ void k1_gen(const int* __restrict__ seed_ptr) {
    int tid = blockIdx.x * blockDim.x + threadIdx.x;   // 131072 threads
    int t = tid & (T_LEN - 1);
    int b = tid >> 13;

    if (t >= NSTEP) {                 // pad steps 8189..8191 (never affect the output)
        g_snsp[b * T_LEN + t] = (uint8_t)(1u | (1u << 2));
        return;
    }

    int seed = *seed_ptr;
    uint32_t key0 = 0u;
    uint32_t key1 = (uint32_t)seed;

    // step key (partitionable split): keys[t] = tf(key, 0, t)
    uint32_t kt0, kt1;
    tf2x32(key0, key1, 0u, (uint32_t)t, kt0, kt1);

    // 3 gumbel bit-words for batch b (partitionable random_bits, 32-bit: o0^o1)
    uint32_t bt[3];
#pragma unroll
    for (int k = 0; k < 3; k++) {
        uint32_t j = (uint32_t)(3 * b + k), o0, o1;
        tf2x32(kt0, kt1, 0u, j, o0, o1);
        bt[k] = o0 ^ o1;
    }

    float lp = g_logits[0], ls = g_logits[1];
    float l21 = g_logits[2], l22 = g_logits[3];

    float g0 = gum_fast(bt[0]), g1 = gum_fast(bt[1]), g2 = gum_fast(bt[2]);
    float v0 = lp + g0, v1 = ls + g1, v2 = lp + g2;
    float w1 = l21 + g1, w2 = l22 + g2;

    float mmin = fminf(fminf(fabsf(v0 - v1), fabsf(v0 - v2)),
                       fminf(fabsf(v1 - v2), fabsf(w1 - w2)));
    if (mmin < 1e-3f) {  // tight argmax margin: redo with correctly-rounded f32 logs
        g0 = gum_precise(bt[0]); g1 = gum_precise(bt[1]); g2 = gum_precise(bt[2]);
        v0 = lp + g0; v1 = ls + g1; v2 = lp + g2;
        w1 = l21 + g1; w2 = l22 + g2;
    }

    // jnp.argmax first-max semantics
    int sn = 0; float best = v0;
    if (v1 > best) { best = v1; sn = 1; }
    if (v2 > best) { sn = 2; }
    int sp = (w1 >= w2) ? 1 : 2;     // row [-inf, w1, w2]

    g_snsp[b * T_LEN + t] = (uint8_t)(sn | (sp << 2));
}

// state cc = (prev1<<2) | prev2 ; special row iff cc == 9 (prev1=2, prev2=1)
__device__ __forceinline__ uint32_t chain_step(uint32_t cc, uint32_t byte) {
    uint32_t s = (cc == 9u) ? ((byte >> 2) & 3u) : (byte & 3u);
    return (s << 2) | (cc >> 2);
}

// ---------------- K2a: speculative segment end-states (9 start states) -------------
__global__ void k2a_end() {
    int tid = blockIdx.x * blockDim.x + threadIdx.x;
    if (tid >= B_CNT * SEG_N * 9) return;
    int s0 = tid % 9;
    int seg = (tid / 9) & (SEG_N - 1);
    int b = tid / (9 * SEG_N);

    uint32_t cc = (((uint32_t)(s0 / 3)) << 2) | (uint32_t)(s0 % 3);
    const uint4* src = (const uint4*)(g_snsp + b * T_LEN + seg * SEG_L);
#pragma unroll
    for (int q = 0; q < 8; q++) {
        uint4 w = __ldg(&src[q]);
        uint32_t ws[4] = {w.x, w.y, w.z, w.w};
#pragma unroll
        for (int wi = 0; wi < 4; wi++) {
            uint32_t word = ws[wi];
#pragma unroll
            for (int bi = 0; bi < 4; bi++)
                cc = chain_step(cc, word >> (8 * bi));
        }
    }
    uint32_t e = (cc >> 2) * 3u + (cc & 3u);   // back to 0..8 index
    g_end[(b * SEG_N + seg) * 16 + s0] = (uint8_t)e;
}

// ---------------- K2b: compose maps + replay segments, emit samples ----------------
__global__ void k2b_chain() {
    __shared__ unsigned long long smap[SEG_N];
    __shared__ int sstart[SEG_N];
    int b = blockIdx.x;
    int seg = threadIdx.x;

    uint4 w = *(const uint4*)(g_end + (b * SEG_N + seg) * 16);
    uint32_t arr[3] = {w.x, w.y, w.z};
    unsigned long long map = 0ull;
#pragma unroll
    for (int i = 0; i < 9; i++) {
        uint32_t e = (arr[i >> 2] >> (8 * (i & 3))) & 0xFu;
        map |= (unsigned long long)e << (4 * i);
    }
    smap[seg] = map;
    __syncthreads();

    if (seg == 0) {
        int c = 4;                               // init state (prev1=1, prev2=1)
#pragma unroll
        for (int s2 = 0; s2 < SEG_N; s2++) {
            sstart[s2] = c;
            c = (int)((smap[s2] >> (4 * c)) & 0xFull);
        }
    }
    __syncthreads();

    int i0 = sstart[seg];
    uint32_t cc = (((uint32_t)(i0 / 3)) << 2) | (uint32_t)(i0 % 3);
    const uint4* src = (const uint4*)(g_snsp + b * T_LEN + seg * SEG_L);
    uint4* dst = (uint4*)(g_smp + b * T_LEN + seg * SEG_L);
#pragma unroll
    for (int q = 0; q < 8; q++) {
        uint4 wv = __ldg(&src[q]);
        uint32_t in[4] = {wv.x, wv.y, wv.z, wv.w};
        uint32_t out[4];
#pragma unroll
        for (int wi = 0; wi < 4; wi++) {
            uint32_t word = in[wi], ow = 0u;
#pragma unroll
            for (int bi = 0; bi < 4; bi++) {
                uint32_t s = (cc == 9u) ? ((word >> (8 * bi + 2)) & 3u)
                                        : ((word >> (8 * bi)) & 3u);
                cc = (s << 2) | (cc >> 2);
                ow |= s << (8 * bi);
            }
            out[wi] = ow;
        }
        dst[q] = make_uint4(out[0], out[1], out[2], out[3]);
    }
}

// ---------------- K4: gather.  out[b,i,to] = x[b,i, to + m] -----------------------
// m = 1 for to==0 (t=1 fixed state), else smp[b][to-1]; mindex = m + t - 1 = to + m
__global__ void k4_gather(const float* __restrict__ x, float* __restrict__ out) {
    int to = blockIdx.x * blockDim.x + threadIdx.x;
    if (to >= 8190) return;
    int bi = blockIdx.y;                 // b*256 + i, 0..4095
    int b = bi >> 8;
    int m = (to == 0) ? 1 : (int)g_smp[b * T_LEN + to - 1];
    out[(size_t)bi * 8190 + to] = x[(size_t)bi * 8192 + to + m];
}

extern "C" void kernel_launch(void* const* d_in, const int* in_sizes, int n_in,
                              void* d_out, int out_size) {
    const float* x = (const float*)d_in[0];
    const int* seed = (const int*)d_in[1];
    float* out = (float*)d_out;

    k0_init<<<1, 1>>>();
    k1_gen<<<512, 256>>>(seed);                  // 131072 threads: (t, b)
    k2a_end<<<36, 256>>>();                      // 9216 threads: (b, seg, s0)
    k2b_chain<<<16, 64>>>();                     // block per batch
    dim3 grid((8190 + 255) / 256, 4096);
    k4_gather<<<grid, 256>>>(x, out);
}

// round 3
// speedup vs baseline: 1.9702x; 1.9702x over previous
#include <cuda_runtime.h>
#include <stdint.h>
#include <math.h>

#define T_LEN 8192
#define B_CNT 16
#define NSTEP 8189            // T-3 markov samples
#define SEG_N 64
#define SEG_L 128             // SEG_N*SEG_L = 8192 (pad last 3 steps)
#define SMP_STRIDE 8208       // 16-byte lead pad + 8192

// ---------------- device scratch (no allocations allowed) ----------------
__device__ uint8_t g_snsp[B_CNT * T_LEN];        // per (b,t): sn | sp<<2
__device__ uint8_t g_smp[B_CNT * SMP_STRIDE];    // [16B pad][8192 resolved samples] per b
__device__ float   g_logits[4];                  // lp, ls, log(8/9-ish), log(1/9-ish)

// ---------------- threefry-2x32 (20 rounds), matches JAX exactly ----------------
__device__ __forceinline__ void tf2x32(uint32_t k0, uint32_t k1,
                                       uint32_t x0, uint32_t x1,
                                       uint32_t& o0, uint32_t& o1) {
    uint32_t ks2 = k0 ^ k1 ^ 0x1BD11BDAu;
    x0 += k0; x1 += k1;
#define RND(r) { x0 += x1; x1 = __funnelshift_l(x1, x1, (r)); x1 ^= x0; }
    RND(13) RND(15) RND(26) RND(6)
    x0 += k1; x1 += ks2 + 1u;
    RND(17) RND(29) RND(16) RND(24)
    x0 += ks2; x1 += k0 + 2u;
    RND(13) RND(15) RND(26) RND(6)
    x0 += k0; x1 += k1 + 3u;
    RND(17) RND(29) RND(16) RND(24)
    x0 += k1; x1 += ks2 + 4u;
    RND(13) RND(15) RND(26) RND(6)
    x0 += ks2; x1 += k0 + 5u;
#undef RND
    o0 = x0; o1 = x1;
}

// JAX uniform(minval=tiny, maxval=1) from raw bits
__device__ __forceinline__ float u_from_bits(uint32_t bits) {
    const float tiny = 1.1754943508222875e-38f;  // FLT_MIN
    float f = __uint_as_float((bits >> 9) | 0x3f800000u) - 1.0f;
    return fmaxf(tiny, f + tiny);
}

__device__ __forceinline__ float gum_fast(uint32_t bits) {
    float u = u_from_bits(bits);
    return -logf(-logf(u));
}

// correctly-rounded f32 gumbel via double logs (used only when argmax margin is tight)
__device__ float gum_precise(uint32_t bits) {
    float u = u_from_bits(bits);
    float inner = (float)log((double)u);
    return -(float)log((double)(-inner));
}

// ---------------- K0: logit constants (built like the numpy reference) -------------
__global__ void k0_init() {
    double p = 0.1;                 // REPLACE_PROB (python double)
    double s = 1.0 - 2.0 * p;
    g_logits[0] = (float)log((double)(float)p);             // log(f32(0.1))
    g_logits[1] = (float)log((double)(float)s);             // log(f32(0.8))
    g_logits[2] = (float)log((double)(float)(s / (p + s))); // special row k=1
    g_logits[3] = (float)log((double)(float)(p / (p + s))); // special row k=2
}

// ---------------- K1: per-(t,b) candidate samples sn / sp (partitionable threefry) --
__global__ void k1_gen(const int* __restrict__ seed_ptr) {
    int tid = blockIdx.x * blockDim.x + threadIdx.x;   // 131072 threads
    int t = tid & (T_LEN - 1);
    int b = tid >> 13;

    if (t >= NSTEP) {                 // pad steps 8189..8191 (never affect the output)
        g_snsp[b * T_LEN + t] = (uint8_t)(1u | (1u << 2));
        return;
    }

    int seed = *seed_ptr;
    uint32_t kt0, kt1;
    tf2x32(0u, (uint32_t)seed, 0u, (uint32_t)t, kt0, kt1);  // keys[t] = tf(key, 0, t)

    uint32_t bt[3];
#pragma unroll
    for (int k = 0; k < 3; k++) {          // bits[(16,3)][3b+k] = o0^o1 of tf(key_t,0,j)
        uint32_t j = (uint32_t)(3 * b + k), o0, o1;
        tf2x32(kt0, kt1, 0u, j, o0, o1);
        bt[k] = o0 ^ o1;
    }

    float lp = g_logits[0], ls = g_logits[1];
    float l21 = g_logits[2], l22 = g_logits[3];

    float g0 = gum_fast(bt[0]), g1 = gum_fast(bt[1]), g2 = gum_fast(bt[2]);
    float v0 = lp + g0, v1 = ls + g1, v2 = lp + g2;
    float w1 = l21 + g1, w2 = l22 + g2;

    float mmin = fminf(fminf(fabsf(v0 - v1), fabsf(v0 - v2)),
                       fminf(fabsf(v1 - v2), fabsf(w1 - w2)));
    if (mmin < 1e-3f) {  // tight argmax margin: redo with correctly-rounded f32 logs
        g0 = gum_precise(bt[0]); g1 = gum_precise(bt[1]); g2 = gum_precise(bt[2]);
        v0 = lp + g0; v1 = ls + g1; v2 = lp + g2;
        w1 = l21 + g1; w2 = l22 + g2;
    }

    int sn = 0; float best = v0;              // jnp.argmax first-max semantics
    if (v1 > best) { best = v1; sn = 1; }
    if (v2 > best) { sn = 2; }
    int sp = (w1 >= w2) ? 1 : 2;              // special row [-inf, w1, w2]

    g_snsp[b * T_LEN + t] = (uint8_t)(sn | (sp << 2));
}

// state cc = (prev1<<2) | prev2 ; special row iff cc == 9 (prev1=2, prev2=1)
__device__ __forceinline__ uint32_t chain_step(uint32_t cc, uint32_t byte) {
    uint32_t s = (cc == 9u) ? ((byte >> 2) & 3u) : (byte & 3u);
    return (s << 2) | (cc >> 2);
}

// ---------------- K2: fused speculative chain (one block per batch) ----------------
// phase A: 64 segs x 9 start states -> end-state table in smem
// phase B: thread 0 composes 64 maps -> per-seg true start state
// phase C: 64 threads replay their segment with the true start, emit samples
__global__ void __launch_bounds__(576) k2_chain() {
    __shared__ uint8_t s_end[SEG_N][9];
    __shared__ int s_start[SEG_N];
    int b = blockIdx.x;
    int tid = threadIdx.x;

    {   // ---- phase A ----
        int seg = tid / 9, s0 = tid % 9;
        uint32_t cc = (((uint32_t)(s0 / 3)) << 2) | (uint32_t)(s0 % 3);
        const uint4* src = (const uint4*)(g_snsp + b * T_LEN + seg * SEG_L);
#pragma unroll
        for (int q = 0; q < 8; q++) {
            uint4 w = __ldg(&src[q]);
            uint32_t ws[4] = {w.x, w.y, w.z, w.w};
#pragma unroll
            for (int wi = 0; wi < 4; wi++) {
                uint32_t word = ws[wi];
#pragma unroll
                for (int bi = 0; bi < 4; bi++)
                    cc = chain_step(cc, word >> (8 * bi));
            }
        }
        s_end[seg][s0] = (uint8_t)((cc >> 2) * 3u + (cc & 3u));
    }
    __syncthreads();

    if (tid == 0) {       // ---- phase B: serial composition across segments ----
        int c = 4;        // init state (prev1=1, prev2=1)
#pragma unroll
        for (int s2 = 0; s2 < SEG_N; s2++) {
            s_start[s2] = c;
            c = (int)s_end[s2][c];
        }
        g_smp[b * SMP_STRIDE + 15] = 1;   // pad byte: m(to=0) = 1
    }
    __syncthreads();

    if (tid < SEG_N) {    // ---- phase C: replay with true start ----
        int seg = tid;
        int i0 = s_start[seg];
        uint32_t cc = (((uint32_t)(i0 / 3)) << 2) | (uint32_t)(i0 % 3);
        const uint4* src = (const uint4*)(g_snsp + b * T_LEN + seg * SEG_L);
        uint4* dst = (uint4*)(g_smp + b * SMP_STRIDE + 16 + seg * SEG_L);
#pragma unroll
        for (int q = 0; q < 8; q++) {
            uint4 wv = __ldg(&src[q]);
            uint32_t in[4] = {wv.x, wv.y, wv.z, wv.w};
            uint32_t out[4];
#pragma unroll
            for (int wi = 0; wi < 4; wi++) {
                uint32_t word = in[wi], ow = 0u;
#pragma unroll
                for (int bi = 0; bi < 4; bi++) {
                    uint32_t s = (cc == 9u) ? ((word >> (8 * bi + 2)) & 3u)
                                            : ((word >> (8 * bi)) & 3u);
                    cc = (s << 2) | (cc >> 2);
                    ow |= s << (8 * bi);
                }
                out[wi] = ow;
            }
            dst[q] = make_uint4(out[0], out[1], out[2], out[3]);
        }
    }
}

// ---------------- K4: vectorized gather (4 outputs / thread) ----------------------
// out[bi, to] = x[bi, to + m(b,to)];  m bytes live at g_smp[b*STRIDE + 15 + to]
__global__ void k4_gather(const float* __restrict__ x, float* __restrict__ out) {
    int t = blockIdx.x * blockDim.x + threadIdx.x;   // quad index: outputs 4t..4t+3
    int bi = blockIdx.y;                             // b*256 + i
    int b = bi >> 8;

    // m bytes for j=0..3 are at byte positions 4t+15 .. 4t+18 -> words t+3, t+4
    const uint32_t* mw = (const uint32_t*)(g_smp + b * SMP_STRIDE);
    uint32_t w0 = __ldg(&mw[t + 3]);
    uint32_t w1 = __ldg(&mw[t + 4]);
    uint32_t mword = __funnelshift_r(w0, w1, 24);    // byte j = m for output 4t+j

    const float* xr = x + (size_t)bi * 8192 + 4 * t;
    float4 v = *(const float4*)xr;                   // 16B aligned
    float v4 = 0.f, v5 = 0.f;
    bool full = (t < 2047);
    if (full) { float2 ex = *(const float2*)(xr + 4); v4 = ex.x; v5 = ex.y; }

    uint32_t m0 = mword & 3u, m1 = (mword >> 8) & 3u,
             m2 = (mword >> 16) & 3u, m3 = (mword >> 24) & 3u;
    float o0 = (m0 == 0u) ? v.x : ((m0 == 1u) ? v.y : v.z);
    float o1 = (m1 == 0u) ? v.y : ((m1 == 1u) ? v.z : v.w);
    float o2 = (m2 == 0u) ? v.z : ((m2 == 1u) ? v.w : v4);
    float o3 = (m3 == 0u) ? v.w : ((m3 == 1u) ? v4 : v5);

    float2* orow = (float2*)(out + (size_t)bi * 8190 + 4 * t);  // 8B aligned
    orow[0] = make_float2(o0, o1);
    if (full) orow[1] = make_float2(o2, o3);
}

extern "C" void kernel_launch(void* const* d_in, const int* in_sizes, int n_in,
                              void* d_out, int out_size) {
    const float* x = (const float*)d_in[0];
    const int* seed = (const int*)d_in[1];
    float* out = (float*)d_out;

    k0_init<<<1, 1>>>();
    k1_gen<<<512, 256>>>(seed);           // 131072 threads: (t, b)
    k2_chain<<<16, 576>>>();              // one block per batch, fused spec+compose+replay
    dim3 grid(8, 4096);                   // 8*256 = 2048 quads per row
    k4_gather<<<grid, 256>>>(x, out);
}

// round 4
// speedup vs baseline: 1.9721x; 1.0009x over previous
#include <cuda_runtime.h>
#include <stdint.h>
#include <math.h>

#define T_LEN 8192
#define B_CNT 16
#define NSTEP 8189            // T-3 markov samples
#define SEG_N 128
#define SEG_L 64              // SEG_N*SEG_L = 8192 (pad last 3 steps)
#define SMP_STRIDE 8208       // 16-byte lead pad + 8192

// ---------------- device scratch (no allocations allowed) ----------------
__device__ uint8_t g_snsp[B_CNT * T_LEN];            // per (b,t): sn | sp<<2
__device__ uint8_t g_end[B_CNT * SEG_N * 16];        // 9 end-states per (b,seg), 16B rows
__device__ uint8_t g_smp[B_CNT * SMP_STRIDE];        // [16B pad][8192 samples] per b
__device__ float   g_logits[4];                      // lp, ls, special row k=1/k=2

// ---------------- threefry-2x32 (20 rounds), matches JAX exactly ----------------
__device__ __forceinline__ void tf2x32(uint32_t k0, uint32_t k1,
                                       uint32_t x0, uint32_t x1,
                                       uint32_t& o0, uint32_t& o1) {
    uint32_t ks2 = k0 ^ k1 ^ 0x1BD11BDAu;
    x0 += k0; x1 += k1;
#define RND(r) { x0 += x1; x1 = __funnelshift_l(x1, x1, (r)); x1 ^= x0; }
    RND(13) RND(15) RND(26) RND(6)
    x0 += k1; x1 += ks2 + 1u;
    RND(17) RND(29) RND(16) RND(24)
    x0 += ks2; x1 += k0 + 2u;
    RND(13) RND(15) RND(26) RND(6)
    x0 += k0; x1 += k1 + 3u;
    RND(17) RND(29) RND(16) RND(24)
    x0 += k1; x1 += ks2 + 4u;
    RND(13) RND(15) RND(26) RND(6)
    x0 += ks2; x1 += k0 + 5u;
#undef RND
    o0 = x0; o1 = x1;
}

// JAX uniform(minval=tiny, maxval=1) from raw bits
__device__ __forceinline__ float u_from_bits(uint32_t bits) {
    const float tiny = 1.1754943508222875e-38f;  // FLT_MIN
    float f = __uint_as_float((bits >> 9) | 0x3f800000u) - 1.0f;
    return fmaxf(tiny, f + tiny);
}

__device__ __forceinline__ float gum_fast(uint32_t bits) {
    float u = u_from_bits(bits);
    return -logf(-logf(u));
}

// correctly-rounded f32 gumbel via double logs (only when argmax margin is tight)
__device__ float gum_precise(uint32_t bits) {
    float u = u_from_bits(bits);
    float inner = (float)log((double)u);
    return -(float)log((double)(-inner));
}

// ---------------- K0: logit constants (built like the numpy reference) -------------
__global__ void k0_init() {
    double p = 0.1;                 // REPLACE_PROB (python double)
    double s = 1.0 - 2.0 * p;
    g_logits[0] = (float)log((double)(float)p);             // log(f32(0.1))
    g_logits[1] = (float)log((double)(float)s);             // log(f32(0.8))
    g_logits[2] = (float)log((double)(float)(s / (p + s))); // special row k=1
    g_logits[3] = (float)log((double)(float)(p / (p + s))); // special row k=2
}

// ---------------- K1: per-(t,b) candidate samples sn / sp (partitionable threefry) --
// block = 16 t-values x 16 batches; keys[t] computed once per t in smem.
__global__ void k1_gen(const int* __restrict__ seed_ptr) {
    __shared__ uint32_t sk0[16], sk1[16];
    int tid = threadIdx.x;
    int tloc = tid & 15;
    int b = tid >> 4;
    int t = blockIdx.x * 16 + tloc;

    if (tid < 16) {       // keys[t] = tf(key, 0, t)  (partitionable split)
        uint32_t a0, a1;
        tf2x32(0u, (uint32_t)(*seed_ptr), 0u, (uint32_t)(blockIdx.x * 16 + tid), a0, a1);
        sk0[tid] = a0; sk1[tid] = a1;
    }
    __syncthreads();

    if (t >= NSTEP) {     // pad steps 8189..8191 (never affect the output)
        g_snsp[b * T_LEN + t] = (uint8_t)(1u | (1u << 2));
        return;
    }
    uint32_t kt0 = sk0[tloc], kt1 = sk1[tloc];

    uint32_t bt[3];
#pragma unroll
    for (int k = 0; k < 3; k++) {   // bits[(16,3)][3b+k] = o0^o1 of tf(key_t, 0, j)
        uint32_t j = (uint32_t)(3 * b + k), o0, o1;
        tf2x32(kt0, kt1, 0u, j, o0, o1);
        bt[k] = o0 ^ o1;
    }

    float lp = g_logits[0], ls = g_logits[1];
    float l21 = g_logits[2], l22 = g_logits[3];

    float g0 = gum_fast(bt[0]), g1 = gum_fast(bt[1]), g2 = gum_fast(bt[2]);
    float v0 = lp + g0, v1 = ls + g1, v2 = lp + g2;
    float w1 = l21 + g1, w2 = l22 + g2;

    float mmin = fminf(fminf(fabsf(v0 - v1), fabsf(v0 - v2)),
                       fminf(fabsf(v1 - v2), fabsf(w1 - w2)));
    if (mmin < 1e-3f) {   // tight argmax margin: redo with correctly-rounded f32 logs
        g0 = gum_precise(bt[0]); g1 = gum_precise(bt[1]); g2 = gum_precise(bt[2]);
        v0 = lp + g0; v1 = ls + g1; v2 = lp + g2;
        w1 = l21 + g1; w2 = l22 + g2;
    }

    int sn = 0; float best = v0;              // jnp.argmax first-max semantics
    if (v1 > best) { best = v1; sn = 1; }
    if (v2 > best) { sn = 2; }
    int sp = (w1 >= w2) ? 1 : 2;              // special row [-inf, w1, w2]

    g_snsp[b * T_LEN + t] = (uint8_t)(sn | (sp << 2));
}

// state cc = (prev1<<2) | prev2 ; special row iff cc == 9 (prev1=2, prev2=1)
__device__ __forceinline__ uint32_t chain_step(uint32_t cc, uint32_t byte) {
    uint32_t s = (cc == 9u) ? ((byte >> 2) & 3u) : (byte & 3u);
    return (s << 2) | (cc >> 2);
}

// ---------------- K2a: speculative segment end-states (9 start states) -------------
__global__ void k2a_end() {
    int gtid = blockIdx.x * blockDim.x + threadIdx.x;   // 18432 threads
    int s0 = gtid % 9;
    int r = gtid / 9;
    int seg = r & (SEG_N - 1);
    int b = r >> 7;

    uint32_t cc = (((uint32_t)(s0 / 3)) << 2) | (uint32_t)(s0 % 3);
    const uint4* src = (const uint4*)(g_snsp + b * T_LEN + seg * SEG_L);
#pragma unroll
    for (int q = 0; q < 4; q++) {
        uint4 w = __ldg(&src[q]);
        uint32_t ws[4] = {w.x, w.y, w.z, w.w};
#pragma unroll
        for (int wi = 0; wi < 4; wi++) {
            uint32_t word = ws[wi];
#pragma unroll
            for (int bi = 0; bi < 4; bi++)
                cc = chain_step(cc, word >> (8 * bi));
        }
    }
    g_end[(b * SEG_N + seg) * 16 + s0] = (uint8_t)((cc >> 2) * 3u + (cc & 3u));
}

// compose two 9-state maps packed as nibbles: (f ∘ g)(i) = f[g[i]]
__device__ __forceinline__ unsigned long long map_comp(unsigned long long f,
                                                       unsigned long long g) {
    unsigned long long r = 0ull;
#pragma unroll
    for (int i = 0; i < 9; i++) {
        uint32_t gi = (uint32_t)(g >> (4 * i)) & 15u;
        uint32_t fi = (uint32_t)(f >> (4 * gi)) & 15u;
        r |= (unsigned long long)fi << (4 * i);
    }
    return r;
}

// ---------------- K2b: Kogge-Stone prefix compose + replay ----------------
__global__ void __launch_bounds__(SEG_N) k2b_chain() {
    __shared__ unsigned long long cur[SEG_N];
    int b = blockIdx.x;
    int seg = threadIdx.x;

    // build my segment's 9->9 map from g_end row
    uint4 w = *(const uint4*)(g_end + (b * SEG_N + seg) * 16);
    uint32_t arr[3] = {w.x, w.y, w.z};
    unsigned long long m = 0ull;
#pragma unroll
    for (int i = 0; i < 9; i++) {
        uint32_t e = (arr[i >> 2] >> (8 * (i & 3))) & 0xFu;
        m |= (unsigned long long)e << (4 * i);
    }
    cur[seg] = m;
    __syncthreads();

    // inclusive prefix: cur[i] = m_i ∘ ... ∘ m_0
#pragma unroll
    for (int d = 1; d < SEG_N; d <<= 1) {
        unsigned long long v = cur[seg];
        if (seg >= d) v = map_comp(v, cur[seg - d]);
        __syncthreads();
        cur[seg] = v;
        __syncthreads();
    }

    if (seg == 0) g_smp[b * SMP_STRIDE + 15] = 1;   // pad byte: m(to=0) = 1

    // replay with true start state: start[seg] = P_{seg-1}(4), start[0] = 4
    int i0 = (seg == 0) ? 4 : (int)((cur[seg - 1] >> 16) & 15ull);
    uint32_t cc = (((uint32_t)(i0 / 3)) << 2) | (uint32_t)(i0 % 3);
    const uint4* src = (const uint4*)(g_snsp + b * T_LEN + seg * SEG_L);
    uint4* dst = (uint4*)(g_smp + b * SMP_STRIDE + 16 + seg * SEG_L);
#pragma unroll
    for (int q = 0; q < 4; q++) {
        uint4 wv = __ldg(&src[q]);
        uint32_t in[4] = {wv.x, wv.y, wv.z, wv.w};
        uint32_t out[4];
#pragma unroll
        for (int wi = 0; wi < 4; wi++) {
            uint32_t word = in[wi], ow = 0u;
#pragma unroll
            for (int bi = 0; bi < 4; bi++) {
                uint32_t s = (cc == 9u) ? ((word >> (8 * bi + 2)) & 3u)
                                        : ((word >> (8 * bi)) & 3u);
                cc = (s << 2) | (cc >> 2);
                ow |= s << (8 * bi);
            }
            out[wi] = ow;
        }
        dst[q] = make_uint4(out[0], out[1], out[2], out[3]);
    }
}

// ---------------- K4: vectorized gather (8 outputs / thread) ----------------------
// out[bi, to] = x[bi, to + m(b,to)];  m bytes live at g_smp[b*STRIDE + 15 + to]
__global__ void k4_gather(const float* __restrict__ x, float* __restrict__ out) {
    int t8 = blockIdx.x * blockDim.x + threadIdx.x;  // oct index: outputs 8t8..8t8+7
    int bi = blockIdx.y;                             // b*256 + i
    int b = bi >> 8;

    // m bytes for j=0..7 at byte positions 8t8+15 .. 8t8+22 -> words 2t8+3..2t8+5
    const uint32_t* mw = (const uint32_t*)(g_smp + b * SMP_STRIDE);
    uint32_t u0 = __ldg(&mw[2 * t8 + 3]);
    uint32_t u1 = __ldg(&mw[2 * t8 + 4]);
    uint32_t u2 = __ldg(&mw[2 * t8 + 5]);
    uint32_t mlo = __funnelshift_r(u0, u1, 24);      // bytes: m0..m3
    uint32_t mhi = __funnelshift_r(u1, u2, 24);      // bytes: m4..m7

    const float* xr = x + (size_t)bi * 8192 + 8 * t8;
    float4 a  = *(const float4*)xr;                  // x[8t8 .. +3]
    float4 bb = *(const float4*)(xr + 4);            // x[8t8+4 .. +7]
    float e0 = 0.f, e1 = 0.f;
    bool full = (t8 < 1023);
    if (full) { float2 e = *(const float2*)(xr + 8); e0 = e.x; e1 = e.y; }

    uint32_t m0 = mlo & 3u, m1 = (mlo >> 8) & 3u, m2 = (mlo >> 16) & 3u, m3 = mlo >> 24;
    uint32_t m4 = mhi & 3u, m5 = (mhi >> 8) & 3u, m6 = (mhi >> 16) & 3u, m7 = mhi >> 24;
    m3 &= 3u; m7 &= 3u;

    float o0 = (m0 == 0u) ? a.x  : ((m0 == 1u) ? a.y  : a.z);
    float o1 = (m1 == 0u) ? a.y  : ((m1 == 1u) ? a.z  : a.w);
    float o2 = (m2 == 0u) ? a.z  : ((m2 == 1u) ? a.w  : bb.x);
    float o3 = (m3 == 0u) ? a.w  : ((m3 == 1u) ? bb.x : bb.y);
    float o4 = (m4 == 0u) ? bb.x : ((m4 == 1u) ? bb.y : bb.z);
    float o5 = (m5 == 0u) ? bb.y : ((m5 == 1u) ? bb.z : bb.w);
    float o6 = (m6 == 0u) ? bb.z : ((m6 == 1u) ? bb.w : e0);
    float o7 = (m7 == 0u) ? bb.w : ((m7 == 1u) ? e0   : e1);

    float* orow = out + (size_t)bi * 8190 + 8 * t8;
    bool al16 = ((bi & 1) == 0);                     // even rows: 16B-aligned stores
    if (full) {
        if (al16) {
            *(float4*)orow       = make_float4(o0, o1, o2, o3);
            *(float4*)(orow + 4) = make_float4(o4, o5, o6, o7);
        } else {
            float2* p = (float2*)orow;
            p[0] = make_float2(o0, o1); p[1] = make_float2(o2, o3);
            p[2] = make_float2(o4, o5); p[3] = make_float2(o6, o7);
        }
    } else {                                         // last oct: 6 outputs (8190 = 8*1023+6)
        if (al16) {
            *(float4*)orow = make_float4(o0, o1, o2, o3);
            *(float2*)(orow + 4) = make_float2(o4, o5);
        } else {
            float2* p = (float2*)orow;
            p[0] = make_float2(o0, o1); p[1] = make_float2(o2, o3);
            p[2] = make_float2(o4, o5);
        }
    }
}

extern "C" void kernel_launch(void* const* d_in, const int* in_sizes, int n_in,
                              void* d_out, int out_size) {
    const float* x = (const float*)d_in[0];
    const int* seed = (const int*)d_in[1];
    float* out = (float*)d_out;

    k0_init<<<1, 1>>>();
    k1_gen<<<512, 256>>>(seed);           // 512 blocks of (16 t x 16 b)
    k2a_end<<<72, 256>>>();               // 18432 threads: (b, seg, s0)
    k2b_chain<<<16, SEG_N>>>();           // one block per batch: prefix + replay
    dim3 grid(4, 4096);                   // 4*256 = 1024 octs per row
    k4_gather<<<grid, 256>>>(x, out);
}

// round 5
// speedup vs baseline: 2.0287x; 1.0287x over previous
#include <cuda_runtime.h>
#include <stdint.h>
#include <math.h>

#define T_LEN 8192
#define B_CNT 16
#define NSTEP 8189            // T-3 markov samples
#define SEG_N 64
#define SEG_L 128             // SEG_N*SEG_L = 8192 (pad last 3 steps)
#define SMP_STRIDE 8208       // 16-byte lead pad + 8192

// ---------------- device scratch (no allocations allowed) ----------------
__device__ uint8_t g_snsp[B_CNT * T_LEN];        // per (b,t): sn | sp<<2
__device__ uint8_t g_smp[B_CNT * SMP_STRIDE];    // [16B pad][8192 samples] per b

// ---------------- threefry-2x32 (20 rounds), matches JAX exactly ----------------
__device__ __forceinline__ void tf2x32(uint32_t k0, uint32_t k1,
                                       uint32_t x0, uint32_t x1,
                                       uint32_t& o0, uint32_t& o1) {
    uint32_t ks2 = k0 ^ k1 ^ 0x1BD11BDAu;
    x0 += k0; x1 += k1;
#define RND(r) { x0 += x1; x1 = __funnelshift_l(x1, x1, (r)); x1 ^= x0; }
    RND(13) RND(15) RND(26) RND(6)
    x0 += k1; x1 += ks2 + 1u;
    RND(17) RND(29) RND(16) RND(24)
    x0 += ks2; x1 += k0 + 2u;
    RND(13) RND(15) RND(26) RND(6)
    x0 += k0; x1 += k1 + 3u;
    RND(17) RND(29) RND(16) RND(24)
    x0 += k1; x1 += ks2 + 4u;
    RND(13) RND(15) RND(26) RND(6)
    x0 += ks2; x1 += k0 + 5u;
#undef RND
    o0 = x0; o1 = x1;
}

// JAX uniform(minval=tiny, maxval=1) from raw bits
__device__ __forceinline__ float u_from_bits(uint32_t bits) {
    const float tiny = 1.1754943508222875e-38f;  // FLT_MIN
    float f = __uint_as_float((bits >> 9) | 0x3f800000u) - 1.0f;
    return fmaxf(tiny, f + tiny);
}

__device__ __forceinline__ float gum_fast(uint32_t bits) {
    float u = u_from_bits(bits);
    return -logf(-logf(u));
}

// correctly-rounded f32 gumbel via double logs (only when argmax margin is tight)
__device__ float gum_precise(uint32_t bits) {
    float u = u_from_bits(bits);
    float inner = (float)log((double)u);
    return -(float)log((double)(-inner));
}

// ---------------- K1: per-(t,b) candidate samples sn / sp (partitionable threefry) --
// block = 16 t-values x 16 batches; keys[t] + the 4 logit constants in smem.
__global__ void k1_gen(const int* __restrict__ seed_ptr) {
    __shared__ uint32_t sk0[16], sk1[16];
    __shared__ float slog[4];
    int tid = threadIdx.x;
    int tloc = tid & 15;
    int b = tid >> 4;
    int t = blockIdx.x * 16 + tloc;

    if (tid < 16) {       // keys[t] = tf(key, 0, t)  (partitionable split)
        uint32_t a0, a1;
        tf2x32(0u, (uint32_t)(*seed_ptr), 0u, (uint32_t)(blockIdx.x * 16 + tid), a0, a1);
        sk0[tid] = a0; sk1[tid] = a1;
    } else if (tid >= 32 && tid < 36) {   // logits, built like the numpy reference
        double p = 0.1, s = 1.0 - 2.0 * 0.1;
        int k = tid - 32;
        double v = (k == 0) ? (double)(float)p
                 : (k == 1) ? (double)(float)s
                 : (k == 2) ? (double)(float)(s / (p + s))
                            : (double)(float)(p / (p + s));
        slog[k] = (float)log(v);
    }
    __syncthreads();

    if (t >= NSTEP) {     // pad steps 8189..8191 (never affect the output)
        g_snsp[b * T_LEN + t] = (uint8_t)(1u | (1u << 2));
        return;
    }
    uint32_t kt0 = sk0[tloc], kt1 = sk1[tloc];

    uint32_t bt[3];
#pragma unroll
    for (int k = 0; k < 3; k++) {   // bits[(16,3)][3b+k] = o0^o1 of tf(key_t, 0, j)
        uint32_t j = (uint32_t)(3 * b + k), o0, o1;
        tf2x32(kt0, kt1, 0u, j, o0, o1);
        bt[k] = o0 ^ o1;
    }

    float lp = slog[0], ls = slog[1], l21 = slog[2], l22 = slog[3];

    float g0 = gum_fast(bt[0]), g1 = gum_fast(bt[1]), g2 = gum_fast(bt[2]);
    float v0 = lp + g0, v1 = ls + g1, v2 = lp + g2;
    float w1 = l21 + g1, w2 = l22 + g2;

    float mmin = fminf(fminf(fabsf(v0 - v1), fabsf(v0 - v2)),
                       fminf(fabsf(v1 - v2), fabsf(w1 - w2)));
    if (mmin < 1e-3f) {   // tight argmax margin: redo with correctly-rounded f32 logs
        g0 = gum_precise(bt[0]); g1 = gum_precise(bt[1]); g2 = gum_precise(bt[2]);
        v0 = lp + g0; v1 = ls + g1; v2 = lp + g2;
        w1 = l21 + g1; w2 = l22 + g2;
    }

    int sn = 0; float best = v0;              // jnp.argmax first-max semantics
    if (v1 > best) { best = v1; sn = 1; }
    if (v2 > best) { sn = 2; }
    int sp = (w1 >= w2) ? 1 : 2;              // special row [-inf, w1, w2]

    g_snsp[b * T_LEN + t] = (uint8_t)(sn | (sp << 2));
}

// compose two 9-state maps packed as nibbles: (f ∘ g)(i) = f[g[i]]
__device__ __forceinline__ unsigned long long map_comp(unsigned long long f,
                                                       unsigned long long g) {
    unsigned long long r = 0ull;
#pragma unroll
    for (int i = 0; i < 9; i++) {
        uint32_t gi = (uint32_t)(g >> (4 * i)) & 15u;
        uint32_t fi = (uint32_t)(f >> (4 * gi)) & 15u;
        r |= (unsigned long long)fi << (4 * i);
    }
    return r;
}

// ---------------- K2: fused speculative chain (one block per batch) ----------------
// phase A: 64 segs x 9 start states -> per-seg 9-state maps (prefetched loads)
// phase B: Kogge-Stone prefix-compose of the 64 maps (6 rounds)
// phase C: 64 threads replay their segment with the true start, emit samples
__global__ void __launch_bounds__(576) k2_chain() {
    __shared__ uint8_t s_end[SEG_N][9];
    __shared__ unsigned long long s_map[SEG_N];
    int b = blockIdx.x;
    int tid = threadIdx.x;

    {   // ---- phase A ----
        int seg = tid / 9, s0 = tid % 9;
        const uint4* src = (const uint4*)(g_snsp + b * T_LEN + seg * SEG_L);
        uint4 w[8];
#pragma unroll
        for (int q = 0; q < 8; q++) w[q] = __ldg(&src[q]);   // MLP=8 up front
        uint32_t cc = (((uint32_t)(s0 / 3)) << 2) | (uint32_t)(s0 % 3);
#pragma unroll
        for (int q = 0; q < 8; q++) {
            uint32_t ws[4] = {w[q].x, w[q].y, w[q].z, w[q].w};
#pragma unroll
            for (int wi = 0; wi < 4; wi++) {
                uint32_t word = ws[wi];
#pragma unroll
                for (int bi = 0; bi < 4; bi++) {
                    uint32_t byte = word >> (8 * bi);
                    uint32_t s = (cc == 9u) ? ((byte >> 2) & 3u) : (byte & 3u);
                    cc = (s << 2) | (cc >> 2);
                }
            }
        }
        s_end[seg][s0] = (uint8_t)((cc >> 2) * 3u + (cc & 3u));
    }
    __syncthreads();

    if (tid < SEG_N) {    // pack the 9 end states into one nibble map
        unsigned long long m = 0ull;
#pragma unroll
        for (int i = 0; i < 9; i++)
            m |= (unsigned long long)s_end[tid][i] << (4 * i);
        s_map[tid] = m;
    }
    __syncthreads();

    // ---- phase B: inclusive prefix s_map[i] = m_i ∘ ... ∘ m_0 ----
#pragma unroll
    for (int d = 1; d < SEG_N; d <<= 1) {
        unsigned long long v;
        if (tid < SEG_N) {
            v = s_map[tid];
            if (tid >= d) v = map_comp(v, s_map[tid - d]);
        }
        __syncthreads();
        if (tid < SEG_N) s_map[tid] = v;
        __syncthreads();
    }

    if (tid == 0) g_smp[b * SMP_STRIDE + 15] = 1;   // pad byte: m(to=0) = 1

    if (tid < SEG_N) {    // ---- phase C: replay with true start ----
        int seg = tid;
        int i0 = (seg == 0) ? 4 : (int)((s_map[seg - 1] >> 16) & 15ull);
        const uint4* src = (const uint4*)(g_snsp + b * T_LEN + seg * SEG_L);
        uint4 w[8];
#pragma unroll
        for (int q = 0; q < 8; q++) w[q] = __ldg(&src[q]);
        uint32_t cc = (((uint32_t)(i0 / 3)) << 2) | (uint32_t)(i0 % 3);
        uint4* dst = (uint4*)(g_smp + b * SMP_STRIDE + 16 + seg * SEG_L);
#pragma unroll
        for (int q = 0; q < 8; q++) {
            uint32_t in[4] = {w[q].x, w[q].y, w[q].z, w[q].w};
            uint32_t out[4];
#pragma unroll
            for (int wi = 0; wi < 4; wi++) {
                uint32_t word = in[wi], ow = 0u;
#pragma unroll
                for (int bi = 0; bi < 4; bi++) {
                    uint32_t s = (cc == 9u) ? ((word >> (8 * bi + 2)) & 3u)
                                            : ((word >> (8 * bi)) & 3u);
                    cc = (s << 2) | (cc >> 2);
                    ow |= s << (8 * bi);
                }
                out[wi] = ow;
            }
            dst[q] = make_uint4(out[0], out[1], out[2], out[3]);
        }
    }
}

// ---------------- K4: vectorized gather (8 outputs / thread) ----------------------
// out[bi, to] = x[bi, to + m(b,to)];  m bytes live at g_smp[b*STRIDE + 15 + to]
__global__ void k4_gather(const float* __restrict__ x, float* __restrict__ out) {
    int t8 = blockIdx.x * blockDim.x + threadIdx.x;  // oct index: outputs 8t8..8t8+7
    int bi = blockIdx.y;                             // b*256 + i
    int b = bi >> 8;

    const uint32_t* mw = (const uint32_t*)(g_smp + b * SMP_STRIDE);
    uint32_t u0 = __ldg(&mw[2 * t8 + 3]);
    uint32_t u1 = __ldg(&mw[2 * t8 + 4]);
    uint32_t u2 = __ldg(&mw[2 * t8 + 5]);
    uint32_t mlo = __funnelshift_r(u0, u1, 24);      // bytes: m0..m3
    uint32_t mhi = __funnelshift_r(u1, u2, 24);      // bytes: m4..m7

    const float* xr = x + (size_t)bi * 8192 + 8 * t8;
    float4 a  = *(const float4*)xr;                  // x[8t8 .. +3]
    float4 bb = *(const float4*)(xr + 4);            // x[8t8+4 .. +7]
    float e0 = 0.f, e1 = 0.f;
    bool full = (t8 < 1023);
    if (full) { float2 e = *(const float2*)(xr + 8); e0 = e.x; e1 = e.y; }

    uint32_t m0 = mlo & 3u, m1 = (mlo >> 8) & 3u, m2 = (mlo >> 16) & 3u, m3 = (mlo >> 24) & 3u;
    uint32_t m4 = mhi & 3u, m5 = (mhi >> 8) & 3u, m6 = (mhi >> 16) & 3u, m7 = (mhi >> 24) & 3u;

    float o0 = (m0 == 0u) ? a.x  : ((m0 == 1u) ? a.y  : a.z);
    float o1 = (m1 == 0u) ? a.y  : ((m1 == 1u) ? a.z  : a.w);
    float o2 = (m2 == 0u) ? a.z  : ((m2 == 1u) ? a.w  : bb.x);
    float o3 = (m3 == 0u) ? a.w  : ((m3 == 1u) ? bb.x : bb.y);
    float o4 = (m4 == 0u) ? bb.x : ((m4 == 1u) ? bb.y : bb.z);
    float o5 = (m5 == 0u) ? bb.y : ((m5 == 1u) ? bb.z : bb.w);
    float o6 = (m6 == 0u) ? bb.z : ((m6 == 1u) ? bb.w : e0);
    float o7 = (m7 == 0u) ? bb.w : ((m7 == 1u) ? e0   : e1);

    float* orow = out + (size_t)bi * 8190 + 8 * t8;
    bool al16 = ((bi & 1) == 0);                     // even rows: 16B-aligned stores
    if (full) {
        if (al16) {
            *(float4*)orow       = make_float4(o0, o1, o2, o3);
            *(float4*)(orow + 4) = make_float4(o4, o5, o6, o7);
        } else {
            float2* p = (float2*)orow;
            p[0] = make_float2(o0, o1); p[1] = make_float2(o2, o3);
            p[2] = make_float2(o4, o5); p[3] = make_float2(o6, o7);
        }
    } else {                                         // last oct: 6 outputs (8190 = 8*1023+6)
        if (al16) {
            *(float4*)orow = make_float4(o0, o1, o2, o3);
            *(float2*)(orow + 4) = make_float2(o4, o5);
        } else {
            float2* p = (float2*)orow;
            p[0] = make_float2(o0, o1); p[1] = make_float2(o2, o3);
            p[2] = make_float2(o4, o5);
        }
    }
}

extern "C" void kernel_launch(void* const* d_in, const int* in_sizes, int n_in,
                              void* d_out, int out_size) {
    const float* x = (const float*)d_in[0];
    const int* seed = (const int*)d_in[1];
    float* out = (float*)d_out;

    k1_gen<<<512, 256>>>(seed);           // 512 blocks of (16 t x 16 b), logits fused
    k2_chain<<<16, 576>>>();              // one block per batch: spec + prefix + replay
    dim3 grid(4, 4096);                   // 4*256 = 1024 octs per row
    k4_gather<<<grid, 256>>>(x, out);
}